// round 11
// baseline (speedup 1.0000x reference)
#include <cuda_runtime.h>
#include <math.h>
#include <stdint.h>

#define NTHREADS 256
#define NTG      128        // threads per group
#define PAIRS    16         // pairs per block
#define PAIRS_G  8          // pairs per group
#define ROWS_G   24         // rows per group
#define NBLK     2048

typedef unsigned long long ull;

// smem layout (floats): 18816 floats -> 3 blocks/SM. Each group gets half
// of every region.
#define EVT_OFF   0          // 2 * 24*176 = 8448
#define FEAT_OFF  8448       // 2 * 24*128 = 6144
#define ABUF_OFF  14592      // 2 * 2112   = 4224
#define SMEM_FLOATS 18816
#define SMEM_BYTES (SMEM_FLOATS*4)
// per-group region sizes (floats)
#define EVTG_SZ   4224
#define FEATG_SZ  3072
#define ABUFG_SZ  2112
// per-group aliases (offsets within the group's EVT region)
#define GH1_O     0          // 24x64 = 1536
#define GH2_O     1536       // 24x64
#define TGTB_O    0          // 16x128 = 2048
#define WQ_O      2048       // 16x128
#define WP_O      0          // 8x128 = 1024 (tgtb dead)
// within group's ABUF region
#define OUTB_O    0          // 8x128 = 1024
#define SC_O      1024       // 16 floats
// within group's FEAT region (feat dead after outb built)
#define HB_O      0          // 8x64 = 512
#define SF_O      512        // 8x64
#define XB_O      1024       // 8x76 = 608 (pad to 640)
#define H1_O      1664       // 8x76
#define H2_O      2304       // 8x64

__device__ __forceinline__ void bsync(int bar) {
    asm volatile("bar.sync %0, %1;" :: "r"(bar), "r"(NTG) : "memory");
}
__device__ __forceinline__ ull pack2(float lo, float hi) {
    ull r; asm("mov.b64 %0, {%1, %2};" : "=l"(r) : "f"(lo), "f"(hi)); return r;
}
__device__ __forceinline__ void unpack2(ull v, float& lo, float& hi) {
    asm("mov.b64 {%0, %1}, %2;" : "=f"(lo), "=f"(hi) : "l"(v));
}
__device__ __forceinline__ void fma2(ull& d, ull a, ull b) {
    asm("fma.rn.f32x2 %0, %1, %2, %0;" : "+l"(d) : "l"(a), "l"(b));
}
__device__ __forceinline__ float fsel4(float4 v, int kk) {
    return (kk==0)?v.x:(kk==1)?v.y:(kk==2)?v.z:v.w;
}

// ---------------------------------------------------------------------------
// Pre-transposed / padded weights ([k][o] layout, zero padded)
// ---------------------------------------------------------------------------
__device__ __align__(16) float g_WT_event[352*192];
__device__ __align__(16) float g_WT_gcn1 [176*64];
__device__ __align__(16) float g_WT_gcn2 [ 64*64];
__device__ __align__(16) float g_WT_att1 [128*128];
__device__ __align__(16) float g_WT_att2 [128*128];
__device__ __align__(16) float g_WT_m1   [128*64];
__device__ __align__(16) float g_WT_m2   [ 64*64];
__device__ __align__(16) float g_WT_mlp1 [76*128];
__device__ __align__(16) float g_WT_mlp2 [76*64];
__device__ __align__(16) float g_ct2     [192];

__global__ void prep_kernel(const float* __restrict__ ew,
                            const float* __restrict__ g1,
                            const float* __restrict__ g2,
                            const float* __restrict__ a1,
                            const float* __restrict__ a2,
                            const float* __restrict__ m1,
                            const float* __restrict__ m2,
                            const float* __restrict__ w1,
                            const float* __restrict__ w2,
                            const float* __restrict__ ph)
{
    int t0 = blockIdx.x*blockDim.x + threadIdx.x;
    int stride = gridDim.x*blockDim.x;
    for (int i = t0; i < 352*192; i += stride) {
        int k = i/192, o = i%192;
        g_WT_event[i] = (k < 347 && o < 172) ? ew[o*347 + k] : 0.f;
    }
    for (int i = t0; i < 176*64; i += stride) {
        int k = i/64, o = i%64;
        g_WT_gcn1[i] = (k < 172) ? g1[o*172 + k] : 0.f;
    }
    for (int i = t0; i < 64*64; i += stride) {
        int k = i/64, o = i%64;
        g_WT_gcn2[i] = g2[o*64 + k];
        g_WT_m2[i]   = m2[o*64 + k];
    }
    for (int i = t0; i < 128*128; i += stride) {
        int k = i/128, o = i%128;
        g_WT_att1[i] = a1[o*128 + k];
        g_WT_att2[i] = a2[o*128 + k];
    }
    for (int i = t0; i < 128*64; i += stride) {
        int k = i/64, o = i%64;
        g_WT_m1[i] = m1[o*128 + k];
    }
    for (int i = t0; i < 76*128; i += stride) {
        int k = i/128, o = i%128;
        g_WT_mlp1[i] = (o < 76) ? w1[o*76 + k] : 0.f;
    }
    for (int i = t0; i < 76*64; i += stride) {
        int k = i/64, o = i%64;
        g_WT_mlp2[i] = w2[o*76 + k];
    }
    for (int o = t0; o < 192; o += stride) {
        float s = 0.f;
        if (o < 172) {
            for (int d = 1; d < 172; d++)
                s += cosf(ph[d]) * ew[o*347 + 175 + d];
        }
        g_ct2[o] = s;
    }
}

// ---------------------------------------------------------------------------
// Direct GEMM, group-local (4 warps, 128 threads).
// Thread (ty,tx): rows [ty*RT,..+RT), cols {g*64+2tx,+1}, g<P.
// ---------------------------------------------------------------------------
template<int NS, int K, int RT, int P, bool RELU, int NREAL>
__device__ __forceinline__ void gemm_direct(
    const float* __restrict__ Wg, const float* __restrict__ bias,
    const float* __restrict__ A, int sa,
    float* __restrict__ C, int sc, int tid, int bar)
{
    const int ty = tid >> 5, tx = tid & 31;
    ull acc[RT][P];
#pragma unroll
    for (int i = 0; i < RT; i++)
#pragma unroll
        for (int g = 0; g < P; g++) acc[i][g] = 0ull;
    const float* wq   = Wg + 2*tx;
    const float* arow = A + ty*RT*sa;
#pragma unroll 1
    for (int k4 = 0; k4 < K; k4 += 4) {
        ull w[4][P];
#pragma unroll
        for (int kk = 0; kk < 4; kk++)
#pragma unroll
            for (int g = 0; g < P; g++)
                w[kk][g] = __ldg(reinterpret_cast<const ull*>(wq + (k4+kk)*NS + g*64));
        float4 av[RT];
#pragma unroll
        for (int i = 0; i < RT; i++)
            av[i] = *reinterpret_cast<const float4*>(arow + i*sa + k4);
#pragma unroll
        for (int kk = 0; kk < 4; kk++)
#pragma unroll
            for (int i = 0; i < RT; i++) {
                float a = fsel4(av[i], kk);
                ull ad = pack2(a, a);
#pragma unroll
                for (int g = 0; g < P; g++) fma2(acc[i][g], ad, w[kk][g]);
            }
    }
#pragma unroll
    for (int i = 0; i < RT; i++)
#pragma unroll
        for (int g = 0; g < P; g++) {
            int col = g*64 + 2*tx;
            float x, y; unpack2(acc[i][g], x, y);
            int row = ty*RT + i;
            if (col < NREAL) {
                float v = x + __ldg(&bias[col]);
                if (RELU) v = fmaxf(v, 0.f);
                C[row*sc + col] = v;
            }
            if (col + 1 < NREAL) {
                float v = y + __ldg(&bias[col+1]);
                if (RELU) v = fmaxf(v, 0.f);
                C[row*sc + col + 1] = v;
            }
        }
    bsync(bar);
}

// ---------------------------------------------------------------------------
// Event generators (group-local: 24 rows / 16 rows)
// ---------------------------------------------------------------------------
struct EventGenA {          // cols [0,176), 24 rows
    const int*   edge_idx;
    const float* edge_embed;
    const float* edge_identify;
    const float* t_records;
    const float* basis_freq;
    const float* phase;
    int g0;                 // group's first pair
    __device__ __forceinline__ void operator()(float* Abuf, int kc, int tid) const {
        for (int idx = tid; idx < ROWS_G*44; idx += NTG) {
            int r = idx / 44, cc = idx - r*44;
            int c = kc + cc;
            int p = r / 3, l = r - p*3;
            int g = g0 + p;
            float v = 0.f;
            if (c < 172) {
                int e = __ldg(&edge_idx[g*3 + l]);
                v = __ldg(&edge_embed[(long)e*172 + c]);
            } else if (c < 175) {
                v = __ldg(&edge_identify[(g*3 + l)*3 + (c - 172)]);
            } else if (c == 175) {
                float dt = __ldg(&t_records[g*3 + 2]) - __ldg(&t_records[g*3 + l]);
                v = __cosf(dt * __ldg(&basis_freq[0]) + __ldg(&phase[0]));
            }
            Abuf[idx] = v;
        }
    }
};

struct EventGenB {          // cols 176+kc.., 16 rows (l != 2)
    const float* t_records;
    const float* basis_freq;
    const float* phase;
    int g0;
    __device__ __forceinline__ void operator()(float* Abuf, int kc, int tid) const {
        for (int idx = tid; idx < 16*44; idx += NTG) {
            int rr = idx / 44, cc = idx - rr*44;
            int c = 176 + kc + cc;
            int p = rr >> 1, l = rr & 1;
            int g = g0 + p;
            float v = 0.f;
            if (c < 347) {
                int d = c - 175;
                float dt = __ldg(&t_records[g*3 + 2]) - __ldg(&t_records[g*3 + l]);
                v = __cosf(dt * __ldg(&basis_freq[d]) + __ldg(&phase[d]));
            }
            Abuf[idx] = v;
        }
    }
};

// Phase 1a: K=176 (4 chunks of 44), M=24 (RT=6), P=3, writes evt (+bias).
__device__ __forceinline__ void gemm_event_a(
    const float* __restrict__ bias,
    float* __restrict__ Abuf, const EventGenA& gen,
    float* __restrict__ C, int tid, int bar)
{
    const int ty = tid >> 5, tx = tid & 31;
    ull acc[6][3];
#pragma unroll
    for (int i = 0; i < 6; i++)
#pragma unroll
        for (int g = 0; g < 3; g++) acc[i][g] = 0ull;

    gen(Abuf, 0, tid);
    bsync(bar);
#pragma unroll 1
    for (int kc = 0; kc < 176; kc += 44) {
        int buf = (kc / 44) & 1;
        const float* cur = Abuf + buf*1056;
        if (kc + 44 < 176) gen(Abuf + (buf^1)*1056, kc + 44, tid);
        const float* wq   = g_WT_event + kc*192 + 2*tx;
        const float* arow = cur + ty*6*44;
#pragma unroll 1
        for (int k4 = 0; k4 < 44; k4 += 4) {
            float4 av[6];
#pragma unroll
            for (int i = 0; i < 6; i++)
                av[i] = *reinterpret_cast<const float4*>(arow + i*44 + k4);
#pragma unroll
            for (int kk = 0; kk < 4; kk++) {
                ull w[3];
#pragma unroll
                for (int g = 0; g < 3; g++)
                    w[g] = __ldg(reinterpret_cast<const ull*>(wq + (k4+kk)*192 + g*64));
#pragma unroll
                for (int i = 0; i < 6; i++) {
                    float a = fsel4(av[i], kk);
                    ull ad = pack2(a, a);
#pragma unroll
                    for (int g = 0; g < 3; g++) fma2(acc[i][g], ad, w[g]);
                }
            }
        }
        bsync(bar);
    }
#pragma unroll
    for (int i = 0; i < 6; i++)
#pragma unroll
        for (int g = 0; g < 3; g++) {
            int col = g*64 + 2*tx;
            float x, y; unpack2(acc[i][g], x, y);
            int row = ty*6 + i;
            if (col < 172)     C[row*176 + col]     = x + __ldg(&bias[col]);
            if (col + 1 < 172) C[row*176 + col + 1] = y + __ldg(&bias[col+1]);
        }
    bsync(bar);
}

// Phase 1b: weight rows 176.., M=16 (RT=4), accumulates into evt rows p*3+l.
__device__ __forceinline__ void gemm_event_b(
    float* __restrict__ Abuf, const EventGenB& gen,
    float* __restrict__ C, int tid, int bar)
{
    const int ty = tid >> 5, tx = tid & 31;
    ull acc[4][3];
#pragma unroll
    for (int i = 0; i < 4; i++)
#pragma unroll
        for (int g = 0; g < 3; g++) acc[i][g] = 0ull;

    gen(Abuf, 0, tid);
    bsync(bar);
#pragma unroll 1
    for (int kc = 0; kc < 176; kc += 44) {
        int buf = (kc / 44) & 1;
        const float* cur = Abuf + buf*704;
        if (kc + 44 < 176) gen(Abuf + (buf^1)*704, kc + 44, tid);
        const float* wq   = g_WT_event + (176 + kc)*192 + 2*tx;
        const float* arow = cur + ty*4*44;
#pragma unroll 1
        for (int k4 = 0; k4 < 44; k4 += 4) {
            float4 av[4];
#pragma unroll
            for (int i = 0; i < 4; i++)
                av[i] = *reinterpret_cast<const float4*>(arow + i*44 + k4);
#pragma unroll
            for (int kk = 0; kk < 4; kk++) {
                ull w[3];
#pragma unroll
                for (int g = 0; g < 3; g++)
                    w[g] = __ldg(reinterpret_cast<const ull*>(wq + (k4+kk)*192 + g*64));
#pragma unroll
                for (int i = 0; i < 4; i++) {
                    float a = fsel4(av[i], kk);
                    ull ad = pack2(a, a);
#pragma unroll
                    for (int g = 0; g < 3; g++) fma2(acc[i][g], ad, w[g]);
                }
            }
        }
        bsync(bar);
    }
#pragma unroll
    for (int i = 0; i < 4; i++)
#pragma unroll
        for (int g = 0; g < 3; g++) {
            int col = g*64 + 2*tx;
            float x, y; unpack2(acc[i][g], x, y);
            int rr = ty*4 + i;
            int row = (rr >> 1)*3 + (rr & 1);
            if (col < 172)     C[row*176 + col]     += x;
            if (col + 1 < 172) C[row*176 + col + 1] += y;
        }
    bsync(bar);
}

// ---------------------------------------------------------------------------
// Dual gine (group-local: 24 rows, RT=6)
// ---------------------------------------------------------------------------
struct GineDualGen {
    const int*   node_idx;
    const float* node_embed;
    const float* evt;   // group's evt, pitch 176
    int g0;
    __device__ __forceinline__ void operator()(float* Abuf, int kc, int tid) const {
        for (int idx = tid; idx < ROWS_G*44; idx += NTG) {
            int r = idx / 44, cc = idx - r*44;
            int c = kc + cc;
            int p = r / 3, l = r - p*3;
            int g = g0 + p;
            float v1 = 0.f, v2 = 0.f;
            if (c < 172) {
                int ns = __ldg(&node_idx[g*6 + 2*l]);
                int nt = __ldg(&node_idx[g*6 + 2*l + 1]);
                float s = __ldg(&node_embed[(long)ns*172 + c]);
                float t = __ldg(&node_embed[(long)nt*172 + c]);
                float e = evt[r*176 + c];
                v1 = s + fmaxf(t + e, 0.f);
                v2 = t + fmaxf(s + e, 0.f);
            }
            Abuf[idx]        = v1;
            Abuf[1056 + idx] = v2;
        }
    }
};

__device__ __forceinline__ void gemm_gine_dual(
    const float* __restrict__ bias,
    float* __restrict__ Abuf, const GineDualGen& gen,
    float* __restrict__ C1, float* __restrict__ C2, int tid, int bar)
{
    const int ty = tid >> 5, tx = tid & 31;
    ull acc1[6], acc2[6];
#pragma unroll
    for (int i = 0; i < 6; i++) { acc1[i] = 0ull; acc2[i] = 0ull; }
#pragma unroll 1
    for (int kc = 0; kc < 176; kc += 44) {
        bsync(bar);
        gen(Abuf, kc, tid);
        bsync(bar);
        const float* wq = g_WT_gcn1 + kc*64 + 2*tx;
        const float* a1row = Abuf + ty*6*44;
        const float* a2row = Abuf + 1056 + ty*6*44;
#pragma unroll 1
        for (int k4 = 0; k4 < 44; k4 += 4) {
            ull w[4];
#pragma unroll
            for (int kk = 0; kk < 4; kk++)
                w[kk] = __ldg(reinterpret_cast<const ull*>(wq + (k4+kk)*64));
#pragma unroll
            for (int i = 0; i < 6; i++) {
                float4 a1 = *reinterpret_cast<const float4*>(a1row + i*44 + k4);
                float4 a2 = *reinterpret_cast<const float4*>(a2row + i*44 + k4);
#pragma unroll
                for (int kk = 0; kk < 4; kk++) {
                    fma2(acc1[i], pack2(fsel4(a1,kk), fsel4(a1,kk)), w[kk]);
                    fma2(acc2[i], pack2(fsel4(a2,kk), fsel4(a2,kk)), w[kk]);
                }
            }
        }
    }
    int col = 2*tx;
    float b0 = __ldg(&bias[col]), b1 = __ldg(&bias[col+1]);
#pragma unroll
    for (int i = 0; i < 6; i++) {
        int row = ty*6 + i;
        float x, y;
        unpack2(acc1[i], x, y);
        C1[row*64 + col]     = fmaxf(x + b0, 0.f);
        C1[row*64 + col + 1] = fmaxf(y + b1, 0.f);
        unpack2(acc2[i], x, y);
        C2[row*64 + col]     = fmaxf(x + b0, 0.f);
        C2[row*64 + col + 1] = fmaxf(y + b1, 0.f);
    }
    bsync(bar);
}

__device__ __forceinline__ void gemm_gcn2_dual(
    const float* __restrict__ bias,
    const float* __restrict__ H1, const float* __restrict__ H2,
    float* __restrict__ feat, int tid, int bar)
{
    const int ty = tid >> 5, tx = tid & 31;
    ull acc1[6], acc2[6];
#pragma unroll
    for (int i = 0; i < 6; i++) { acc1[i] = 0ull; acc2[i] = 0ull; }
    const float* wq = g_WT_gcn2 + 2*tx;
#pragma unroll 1
    for (int k4 = 0; k4 < 64; k4 += 4) {
        ull w[4];
#pragma unroll
        for (int kk = 0; kk < 4; kk++)
            w[kk] = __ldg(reinterpret_cast<const ull*>(wq + (k4+kk)*64));
#pragma unroll
        for (int i = 0; i < 6; i++) {
            float4 a1 = *reinterpret_cast<const float4*>(H1 + (ty*6+i)*64 + k4);
            float4 a2 = *reinterpret_cast<const float4*>(H2 + (ty*6+i)*64 + k4);
#pragma unroll
            for (int kk = 0; kk < 4; kk++) {
                fma2(acc1[i], pack2(fsel4(a1,kk), fsel4(a1,kk)), w[kk]);
                fma2(acc2[i], pack2(fsel4(a2,kk), fsel4(a2,kk)), w[kk]);
            }
        }
    }
    bsync(bar);
    int col = 2*tx;
    float b0 = __ldg(&bias[col]), b1 = __ldg(&bias[col+1]);
#pragma unroll
    for (int i = 0; i < 6; i++) {
        int row = ty*6 + i;
        float x, y;
        unpack2(acc1[i], x, y);
        feat[row*128 + col]      = x + b0;
        feat[row*128 + col + 1]  = y + b1;
        unpack2(acc2[i], x, y);
        feat[row*128 + 64 + col]     = x + b0;
        feat[row*128 + 64 + col + 1] = y + b1;
    }
    bsync(bar);
}

// ---------------------------------------------------------------------------
// Fused main kernel: 2 independent 4-warp groups, 8 pairs each.
// ---------------------------------------------------------------------------
__global__ void __launch_bounds__(NTHREADS, 3)
fused_kernel(const int*   __restrict__ node_idx,
             const int*   __restrict__ edge_idx,
             const int*   __restrict__ cat_feat,
             const float* __restrict__ t_records,
             const float* __restrict__ edge_identify,
             const float* __restrict__ node_embed,
             const float* __restrict__ edge_embed,
             const float* __restrict__ basis_freq,
             const float* __restrict__ phase,
             const float* __restrict__ lin_event_b,
             const float* __restrict__ gcn_b1,
             const float* __restrict__ gcn_b2,
             const float* __restrict__ att_w1_b,
             const float* __restrict__ att_w2_b,
             const float* __restrict__ att_m1_b,
             const float* __restrict__ att_m2_b,
             const float* __restrict__ mlp_b1,
             const float* __restrict__ mlp_b2,
             const float* __restrict__ mlp_w3,
             const float* __restrict__ mlp_b3,
             float*       __restrict__ out)
{
    extern __shared__ float sm[];
    const int wg   = threadIdx.x >> 7;         // group 0/1
    const int tid  = threadIdx.x & (NTG-1);    // 0..127 within group
    const int bar  = 1 + wg;                   // named barrier id
    const int g0   = blockIdx.x * PAIRS + wg * PAIRS_G;

    float* evt  = sm + EVT_OFF  + wg*EVTG_SZ;
    float* feat = sm + FEAT_OFF + wg*FEATG_SZ;
    float* Abuf = sm + ABUF_OFF + wg*ABUFG_SZ;

    // ---- Phase 1a/1b/1c: event linear ----
    EventGenA ega{edge_idx, edge_embed, edge_identify, t_records, basis_freq, phase, g0};
    gemm_event_a(lin_event_b, Abuf, ega, evt, tid, bar);
    EventGenB egb{t_records, basis_freq, phase, g0};
    gemm_event_b(Abuf, egb, evt, tid, bar);
    for (int idx = tid; idx < PAIRS_G*172; idx += NTG) {
        int p = idx / 172, c = idx - p*172;
        evt[(p*3 + 2)*176 + c] += __ldg(&g_ct2[c]);
    }
    bsync(bar);

    // ---- Phase 2/3: dual gine + dual gcn2 ----
    GineDualGen gg{node_idx, node_embed, evt, g0};
    gemm_gine_dual(gcn_b1, Abuf, gg, evt + GH1_O, evt + GH2_O, tid, bar);
    gemm_gcn2_dual(gcn_b2, evt + GH1_O, evt + GH2_O, feat, tid, bar);

    // ---- Phase 4: attention ----
    float* tgtb = evt + TGTB_O;
    for (int idx = tid; idx < 16*128; idx += NTG) {
        int r = idx >> 7, c = idx & 127;
        tgtb[idx] = feat[((r >> 1)*3 + (r & 1))*128 + c];
    }
    bsync(bar);
    float* Wq = evt + WQ_O;
    gemm_direct<128,128,4,2,false,128>(g_WT_att2, att_w2_b, tgtb, 128, Wq, 128, tid, bar);
    float* Wp = evt + WP_O;   // overwrites tgtb (dead)
    gemm_direct<128,128,2,2,false,128>(g_WT_att1, att_w1_b, feat + 256, 384, Wp, 128, tid, bar);

    float* scb = Abuf + SC_O;
    {
        int pk = tid >> 3, sub = tid & 7;   // pk 0..15
        int p = pk >> 1, k = pk & 1;
        float s = 0.f;
        for (int j = sub; j < 128; j += 8)
            s += Wp[p*128 + j] * Wq[(2*p + k)*128 + j];
        s += __shfl_down_sync(0xffffffffu, s, 4, 8);
        s += __shfl_down_sync(0xffffffffu, s, 2, 8);
        s += __shfl_down_sync(0xffffffffu, s, 1, 8);
        if (sub == 0) scb[pk] = s;
    }
    bsync(bar);
    if (tid < PAIRS_G) {
        float s0 = scb[2*tid], s1 = scb[2*tid + 1];
        float m = fmaxf(s0, s1);
        float e0 = __expf(s0 - m), e1 = __expf(s1 - m);
        float inv = 1.f / (e0 + e1);
        scb[2*tid]     = e0 * inv;
        scb[2*tid + 1] = e1 * inv;
    }
    bsync(bar);
    float* outb = Abuf + OUTB_O;
    for (int idx = tid; idx < PAIRS_G*128; idx += NTG) {
        int p = idx >> 7, c = idx & 127;
        outb[idx] = feat[(p*3 + 2)*128 + c]
                  + scb[2*p]     * Wq[(2*p)*128 + c]
                  + scb[2*p + 1] * Wq[(2*p + 1)*128 + c];
    }
    bsync(bar);

    float* hb = feat + HB_O;
    float* sf = feat + SF_O;
    gemm_direct<64,128,2,1,true,64>(g_WT_m1, att_m1_b, outb, 128, hb, 64, tid, bar);
    gemm_direct<64,64,2,1,false,64>(g_WT_m2, att_m2_b, hb, 64, sf, 64, tid, bar);

    // ---- Phase 5: MLP tail (coalesced GEMMs) ----
    float* xb  = feat + XB_O;
    float* h1b = feat + H1_O;
    float* h2b = feat + H2_O;
    for (int idx = tid; idx < PAIRS_G*76; idx += NTG) {
        int p = idx / 76, c = idx - p*76;
        float v;
        if (c < 64) v = sf[p*64 + c];
        else        v = (__ldg(&cat_feat[g0 + p]) == (c - 64)) ? 1.f : 0.f;
        xb[idx] = v;
    }
    bsync(bar);
    gemm_direct<128,76,2,2,true,76>(g_WT_mlp1, mlp_b1, xb, 76, h1b, 76, tid, bar);
    gemm_direct<64,76,2,1,true,64>(g_WT_mlp2, mlp_b2, h1b, 76, h2b, 64, tid, bar);

    if (tid < PAIRS_G) {
        float z = __ldg(&mlp_b3[0]);
        const float* x = h2b + tid*64;
#pragma unroll 4
        for (int k = 0; k < 64; k++) z += x[k] * __ldg(&mlp_w3[k]);
        out[g0 + tid] = 1.f / (1.f + __expf(-z));
    }
}

// ---------------------------------------------------------------------------
// Launch
// ---------------------------------------------------------------------------
extern "C" void kernel_launch(void* const* d_in, const int* in_sizes, int n_in,
                              void* d_out, int out_size)
{
    const int*   node_idx      = (const int*)  d_in[0];
    const int*   edge_idx      = (const int*)  d_in[1];
    const int*   cat_feat      = (const int*)  d_in[2];
    const float* t_records     = (const float*)d_in[3];
    const float* edge_identify = (const float*)d_in[4];
    // d_in[5] = cut_time_l (unused by reference)
    const float* node_embed    = (const float*)d_in[6];
    const float* edge_embed    = (const float*)d_in[7];
    const float* basis_freq    = (const float*)d_in[8];
    const float* phase         = (const float*)d_in[9];
    const float* lin_event_w   = (const float*)d_in[10];
    const float* lin_event_b   = (const float*)d_in[11];
    const float* gcn_w1        = (const float*)d_in[12];
    const float* gcn_b1        = (const float*)d_in[13];
    const float* gcn_w2        = (const float*)d_in[14];
    const float* gcn_b2        = (const float*)d_in[15];
    const float* att_w1_w      = (const float*)d_in[16];
    const float* att_w1_b      = (const float*)d_in[17];
    const float* att_w2_w      = (const float*)d_in[18];
    const float* att_w2_b      = (const float*)d_in[19];
    const float* att_m1_w      = (const float*)d_in[20];
    const float* att_m1_b      = (const float*)d_in[21];
    const float* att_m2_w      = (const float*)d_in[22];
    const float* att_m2_b      = (const float*)d_in[23];
    const float* mlp_w1        = (const float*)d_in[24];
    const float* mlp_b1        = (const float*)d_in[25];
    const float* mlp_w2        = (const float*)d_in[26];
    const float* mlp_b2        = (const float*)d_in[27];
    const float* mlp_w3        = (const float*)d_in[28];
    const float* mlp_b3        = (const float*)d_in[29];
    float* outp = (float*)d_out;

    cudaFuncSetAttribute(fused_kernel,
                         cudaFuncAttributeMaxDynamicSharedMemorySize, SMEM_BYTES);

    prep_kernel<<<128, 256>>>(lin_event_w, gcn_w1, gcn_w2,
                              att_w1_w, att_w2_w, att_m1_w, att_m2_w,
                              mlp_w1, mlp_w2, phase);

    fused_kernel<<<NBLK, NTHREADS, SMEM_BYTES>>>(
        node_idx, edge_idx, cat_feat, t_records, edge_identify,
        node_embed, edge_embed, basis_freq, phase,
        lin_event_b, gcn_b1, gcn_b2,
        att_w1_b, att_w2_b, att_m1_b, att_m2_b,
        mlp_b1, mlp_b2, mlp_w3, mlp_b3,
        outp);
}